// round 4
// baseline (speedup 1.0000x reference)
#include <cuda_runtime.h>
#include <cstdint>

typedef unsigned long long ull;

#define IMG_W 512
#define OUT_W 507
#define NSTR  3       // strips per image
#define STRIP 169     // output rows per strip (3*169 = 507 exact)
#define NROWS 174     // input rows per strip (STRIP + 5), divisible by 6
#define NB_MM 1184

// ---------------- device-global scratch (no allocs) --------------------------
__device__ float    g_mn[NB_MM], g_mx[NB_MM];
__device__ float    g_part[512];
__device__ unsigned g_done;          // zero-init; last block resets each run

// ---------------- packed f32x2 helpers (sm_103a) ------------------------------
static __device__ __forceinline__ ull pk2(float a, float b){
    ull r; asm("mov.b64 %0, {%1, %2};" : "=l"(r) : "f"(a), "f"(b)); return r;
}
static __device__ __forceinline__ ull mul2(ull a, ull b){
    ull r; asm("mul.rn.f32x2 %0, %1, %2;" : "=l"(r) : "l"(a), "l"(b)); return r;
}
static __device__ __forceinline__ ull add2(ull a, ull b){
    ull r; asm("add.rn.f32x2 %0, %1, %2;" : "=l"(r) : "l"(a), "l"(b)); return r;
}
static __device__ __forceinline__ ull fma2(ull a, ull b, ull c){
    ull r; asm("fma.rn.f32x2 %0, %1, %2, %3;" : "=l"(r) : "l"(a), "l"(b), "l"(c)); return r;
}
static __device__ __forceinline__ float lo2(ull a){ return __uint_as_float((unsigned)a); }
static __device__ __forceinline__ float hi2(ull a){ return __uint_as_float((unsigned)(a >> 32)); }
static __device__ __forceinline__ void pref2(const float* p){
    asm volatile("prefetch.global.L2 [%0];" :: "l"(p));
}

// ---------------- gaussian weights (w_size=6, sigma=1.5, normalized) ---------
#define GW0 0.03802585f
#define GW1 0.11551231f
#define GW2 0.22498725f
#define GW3 0.28097506f

// ---------------- min/max partials kernel -------------------------------------
__global__ void k_minmax(const float4* __restrict__ x, int n4){
    float mn = 3.4028235e38f, mx = -3.4028235e38f;
    int stride = gridDim.x * blockDim.x;
    for (int i = blockIdx.x * blockDim.x + threadIdx.x; i < n4; i += stride){
        float4 v = x[i];
        mn = fminf(mn, fminf(fminf(v.x, v.y), fminf(v.z, v.w)));
        mx = fmaxf(mx, fmaxf(fmaxf(v.x, v.y), fmaxf(v.z, v.w)));
    }
    #pragma unroll
    for (int o = 16; o > 0; o >>= 1){
        mn = fminf(mn, __shfl_xor_sync(0xFFFFFFFFu, mn, o));
        mx = fmaxf(mx, __shfl_xor_sync(0xFFFFFFFFu, mx, o));
    }
    __shared__ float smn[8], smx[8];
    int wid = threadIdx.x >> 5, lane = threadIdx.x & 31;
    if (lane == 0){ smn[wid] = mn; smx[wid] = mx; }
    __syncthreads();
    if (threadIdx.x == 0){
        mn = smn[0]; mx = smx[0];
        #pragma unroll
        for (int w = 1; w < 8; ++w){ mn = fminf(mn, smn[w]); mx = fmaxf(mx, smx[w]); }
        g_mn[blockIdx.x] = mn;
        g_mx[blockIdx.x] = mx;
    }
}

// scalar 6-tap with immediate weights -> FFMA-imm (rt=1). taps [GW0,GW1,GW2,GW3,GW2,GW1]
#define SCONV(m0,m1,m2,m3,m4,m5) \
    fmaf((m5), GW1, fmaf((m4), GW2, fmaf((m3), GW3, fmaf((m2), GW2, fmaf((m1), GW1, (m0) * GW0)))))

// load one input row (both tensors) into register set S (S literal 0..2)
// xr/yr point at this thread's o0 within the row; d1..d3 are byte deltas.
#define LOADROW(S, XR, YR) do { \
    rx[S][0] = *(const float2*)(XR); \
    rx[S][1] = *(const float2*)((const char*)(XR) + d1); \
    rx[S][2] = *(const float2*)((const char*)(XR) + d2); \
    rx[S][3] = *(const float2*)((const char*)(XR) + d3); \
    ry[S][0] = *(const float2*)(YR); \
    ry[S][1] = *(const float2*)((const char*)(YR) + d1); \
    ry[S][2] = *(const float2*)((const char*)(YR) + d2); \
    ry[S][3] = *(const float2*)((const char*)(YR) + d3); \
} while(0)

// One row-step. P literal 0..5; computes input row i=I6+P from set P%3,
// LDG row i+2 into set (P+2)%3, L2-prefetch row i+6, emits output row i-5.
// xr,yr track row i+2; xp,yp track row i+6.
#define ROW_STEP(P, I6) do { \
    const int i_ = (I6) + (P); \
    if (i_ + 6 < NROWS){ pref2(xp); pref2(yp); xp += IMG_W; yp += IMG_W; } \
    if (i_ + 2 < NROWS){ LOADROW(((P)+2)%3, xr, yr); xr += IMG_W; yr += IMG_W; } \
    { \
        float2 X0_ = rx[(P)%3][0], X1_ = rx[(P)%3][1], X2_ = rx[(P)%3][2], X3_ = rx[(P)%3][3]; \
        float2 Y0_ = ry[(P)%3][0], Y1_ = ry[(P)%3][1], Y2_ = ry[(P)%3][2], Y3_ = ry[(P)%3][3]; \
        ull xp0_ = pk2(X0_.x, X0_.y), xp1_ = pk2(X1_.x, X1_.y); \
        ull xp2_ = pk2(X2_.x, X2_.y), xp3_ = pk2(X3_.x, X3_.y); \
        ull yp0_ = pk2(Y0_.x, Y0_.y), yp1_ = pk2(Y1_.x, Y1_.y); \
        ull yp2_ = pk2(Y2_.x, Y2_.y), yp3_ = pk2(Y3_.x, Y3_.y); \
        ull pp0_ = fma2(yp0_, yp0_, mul2(xp0_, xp0_)); \
        ull pp1_ = fma2(yp1_, yp1_, mul2(xp1_, xp1_)); \
        ull pp2_ = fma2(yp2_, yp2_, mul2(xp2_, xp2_)); \
        ull pp3_ = fma2(yp3_, yp3_, mul2(xp3_, xp3_)); \
        ull qq0_ = mul2(xp0_, yp0_), qq1_ = mul2(xp1_, yp1_); \
        ull qq2_ = mul2(xp2_, yp2_), qq3_ = mul2(xp3_, yp3_); \
        ring[(P)][0] = SCONV(X0_.x, X0_.y, X1_.x, X1_.y, X2_.x, X2_.y); \
        ring[(P)][1] = SCONV(X0_.y, X1_.x, X1_.y, X2_.x, X2_.y, X3_.x); \
        ring[(P)][2] = SCONV(Y0_.x, Y0_.y, Y1_.x, Y1_.y, Y2_.x, Y2_.y); \
        ring[(P)][3] = SCONV(Y0_.y, Y1_.x, Y1_.y, Y2_.x, Y2_.y, Y3_.x); \
        ring[(P)][4] = SCONV(lo2(pp0_), hi2(pp0_), lo2(pp1_), hi2(pp1_), lo2(pp2_), hi2(pp2_)); \
        ring[(P)][5] = SCONV(hi2(pp0_), lo2(pp1_), hi2(pp1_), lo2(pp2_), hi2(pp2_), lo2(pp3_)); \
        ring[(P)][6] = SCONV(lo2(qq0_), hi2(qq0_), lo2(qq1_), hi2(qq1_), lo2(qq2_), hi2(qq2_)); \
        ring[(P)][7] = SCONV(hi2(qq0_), lo2(qq1_), hi2(qq1_), lo2(qq2_), hi2(qq2_), lo2(qq3_)); \
    } \
    if (i_ >= 5){ \
        float vv_[8]; \
        _Pragma("unroll") \
        for (int j_ = 0; j_ < 8; ++j_) \
            vv_[j_] = SCONV(ring[((P)+1)%6][j_], ring[((P)+2)%6][j_], ring[((P)+3)%6][j_], \
                            ring[((P)+4)%6][j_], ring[((P)+5)%6][j_], ring[(P)][j_]); \
        ull v0_ = pk2(vv_[0], vv_[1]); \
        ull v1_ = pk2(vv_[2], vv_[3]); \
        ull v2_ = pk2(vv_[4], vv_[5]); \
        ull v3_ = pk2(vv_[6], vv_[7]); \
        ull mu12_ = mul2(v0_, v1_); \
        ull msum_ = fma2(v1_, v1_, mul2(v0_, v0_)); \
        ull t1_ = fma2(mu12_, NTWO, fma2(v3_, TWO, C2p)); \
        ull t2_ = fma2(msum_, NONE, add2(v2_, C2p)); \
        ull num_ = mul2(fma2(mu12_, TWO, C1p), t1_); \
        ull den_ = mul2(add2(msum_, C1p), t2_); \
        float nl_ = lo2(num_), nh_ = hi2(num_); \
        float dl_ = lo2(den_), dh_ = hi2(den_); \
        if (hi_ok)      acc += __fdividef(fmaf(nl_, dh_, nh_ * dl_), dl_ * dh_); \
        else if (lo_ok) acc += __fdividef(nl_, dl_); \
    } \
} while(0)

__global__ void __launch_bounds__(256)
k_ssim(const float* __restrict__ X, const float* __restrict__ Y,
       float* __restrict__ out, int nblk, double inv_n){
    __shared__ float    smn[8], smx[8], sC[2];
    __shared__ double   sd[8];
    __shared__ unsigned s_tick;

    const int tid   = threadIdx.x;
    const int c0    = tid * 2;
    const int bx    = blockIdx.x;
    const int strip = bx % NSTR;
    const int img   = bx / NSTR;
    const int base  = strip * STRIP;
    const float* xi = X + (size_t)img * (IMG_W * IMG_W);
    const float* yi = Y + (size_t)img * (IMG_W * IMG_W);
    const bool lo_ok = (c0     < OUT_W);
    const bool hi_ok = (c0 + 1 < OUT_W);

    // clamped column offsets (edge threads read in-bounds garbage; outputs masked)
    const int o0 = c0;
    const int d1 = (min(c0 + 2, 510) - c0) * 4;   // byte deltas
    const int d2 = (min(c0 + 4, 510) - c0) * 4;
    const int d3 = (min(c0 + 6, 510) - c0) * 4;

    // running row pointers: xr/yr -> next LDG row (starts at base+2);
    // xp/yp -> next prefetch row (starts at base+6)
    const float* xr = xi + (size_t)(base + 2) * IMG_W + o0;
    const float* yr = yi + (size_t)(base + 2) * IMG_W + o0;
    const float* xp = xi + (size_t)(base + 6) * IMG_W + o0;
    const float* yp = yi + (size_t)(base + 6) * IMG_W + o0;

    // ---- reduce min/max partials -> C1, C2 ----
    {
        float mn = 3.4028235e38f, mx = -3.4028235e38f;
        for (int i = tid; i < NB_MM; i += 256){
            mn = fminf(mn, g_mn[i]);
            mx = fmaxf(mx, g_mx[i]);
        }
        #pragma unroll
        for (int o = 16; o > 0; o >>= 1){
            mn = fminf(mn, __shfl_xor_sync(0xFFFFFFFFu, mn, o));
            mx = fmaxf(mx, __shfl_xor_sync(0xFFFFFFFFu, mx, o));
        }
        int wid = tid >> 5, lane = tid & 31;
        if (lane == 0){ smn[wid] = mn; smx[wid] = mx; }
    }

    // register pipeline: 3 rotating row sets
    float2 rx[3][4], ry[3][4];
    {
        const float* x0 = xi + (size_t)base * IMG_W + o0;
        const float* y0 = yi + (size_t)base * IMG_W + o0;
        LOADROW(0, x0, y0);
        LOADROW(1, x0 + IMG_W, y0 + IMG_W);
        #pragma unroll
        for (int r = 2; r < 6; ++r){
            pref2(x0 + (size_t)r * IMG_W);
            pref2(y0 + (size_t)r * IMG_W);
        }
    }

    __syncthreads();
    if (tid == 0){
        float mn = smn[0], mx = smx[0];
        #pragma unroll
        for (int w = 1; w < 8; ++w){ mn = fminf(mn, smn[w]); mx = fmaxf(mx, smx[w]); }
        float Ldyn = (mx > 128.0f ? 255.0f : 1.0f) - (mn < -0.5f ? -1.0f : 0.0f);
        sC[0] = (0.01f * Ldyn) * (0.01f * Ldyn);
        sC[1] = (0.03f * Ldyn) * (0.03f * Ldyn);
    }
    __syncthreads();

    const float C1 = sC[0], C2 = sC[1];
    const ull C1p = pk2(C1, C1),   C2p = pk2(C2, C2);
    const ull TWO = pk2(2.0f, 2.0f), NTWO = pk2(-2.0f, -2.0f), NONE = pk2(-1.0f, -1.0f);

    float ring[6][8];
    float acc = 0.0f;

    #pragma unroll 1
    for (int i6 = 0; i6 < NROWS; i6 += 6){
        ROW_STEP(0, i6);
        ROW_STEP(1, i6);
        ROW_STEP(2, i6);
        ROW_STEP(3, i6);
        ROW_STEP(4, i6);
        ROW_STEP(5, i6);
    }

    // ---- block reduction -> partial; last block finishes ----
    #pragma unroll
    for (int o = 16; o > 0; o >>= 1)
        acc += __shfl_xor_sync(0xFFFFFFFFu, acc, o);
    const int wid = tid >> 5, lane = tid & 31;
    if (lane == 0) smn[wid] = acc;
    __syncthreads();
    if (tid == 0){
        float s = smn[0];
        #pragma unroll
        for (int w = 1; w < 8; ++w) s += smn[w];
        g_part[bx] = s;
        __threadfence();
        s_tick = atomicAdd(&g_done, 1u);
    }
    __syncthreads();

    if (s_tick == (unsigned)(nblk - 1)){
        double s = 0.0;
        for (int i = tid; i < nblk; i += 256) s += (double)g_part[i];
        #pragma unroll
        for (int o = 16; o > 0; o >>= 1)
            s += __shfl_xor_sync(0xFFFFFFFFu, s, o);
        if (lane == 0) sd[wid] = s;
        __syncthreads();
        if (tid == 0){
            double t = 0.0;
            #pragma unroll
            for (int w = 0; w < 8; ++w) t += sd[w];
            out[0] = (float)((1.0 - t * inv_n) * 0.5);
            g_done = 0u;   // reset for next graph replay
        }
    }
}

// ---------------- launch --------------------------------------------------------
extern "C" void kernel_launch(void* const* d_in, const int* in_sizes, int n_in,
                              void* d_out, int out_size){
    const float* X = (const float*)d_in[0];  // y_pred
    const float* Y = (const float*)d_in[1];  // y_true

    const int nelem = in_sizes[0];
    const int nimg  = nelem / (IMG_W * IMG_W);
    const int nblk  = NSTR * nimg;
    const double n_out = (double)nimg * (double)OUT_W * (double)OUT_W;

    k_minmax<<<NB_MM, 256>>>((const float4*)X, nelem / 4);
    k_ssim<<<nblk, 256>>>(X, Y, (float*)d_out, nblk, 1.0 / n_out);
}

// round 5
// speedup vs baseline: 1.4894x; 1.4894x over previous
#include <cuda_runtime.h>
#include <cstdint>

typedef unsigned long long ull;

#define IMG_W 512
#define OUT_W 507
#define NSTR  3       // strips per image
#define STRIP 169     // output rows per strip (3*169 = 507 exact)
#define NROWS 174     // input rows per strip (STRIP + 5), divisible by 6
#define NB_MM 1184

// ---------------- device-global scratch (no allocs) --------------------------
__device__ float    g_mn[NB_MM], g_mx[NB_MM];
__device__ float    g_part[512];
__device__ unsigned g_done;          // zero-init; last block resets each run

// ---------------- packed f32x2 helpers (sm_103a) ------------------------------
static __device__ __forceinline__ ull pk2(float a, float b){
    ull r; asm("mov.b64 %0, {%1, %2};" : "=l"(r) : "f"(a), "f"(b)); return r;
}
static __device__ __forceinline__ ull mul2(ull a, ull b){
    ull r; asm("mul.rn.f32x2 %0, %1, %2;" : "=l"(r) : "l"(a), "l"(b)); return r;
}
static __device__ __forceinline__ ull add2(ull a, ull b){
    ull r; asm("add.rn.f32x2 %0, %1, %2;" : "=l"(r) : "l"(a), "l"(b)); return r;
}
static __device__ __forceinline__ ull fma2(ull a, ull b, ull c){
    ull r; asm("fma.rn.f32x2 %0, %1, %2, %3;" : "=l"(r) : "l"(a), "l"(b), "l"(c)); return r;
}
static __device__ __forceinline__ float lo2(ull a){ return __uint_as_float((unsigned)a); }
static __device__ __forceinline__ float hi2(ull a){ return __uint_as_float((unsigned)(a >> 32)); }
static __device__ __forceinline__ void pref2(const float* p){
    asm volatile("prefetch.global.L2 [%0];" :: "l"(p));
}

// ---------------- gaussian weights (w_size=6, sigma=1.5, normalized) ---------
#define GW0 0.03802585f
#define GW1 0.11551231f
#define GW2 0.22498725f
#define GW3 0.28097506f

// ---------------- min/max partials kernel -------------------------------------
__global__ void k_minmax(const float4* __restrict__ x, int n4){
    float mn = 3.4028235e38f, mx = -3.4028235e38f;
    int stride = gridDim.x * blockDim.x;
    for (int i = blockIdx.x * blockDim.x + threadIdx.x; i < n4; i += stride){
        float4 v = x[i];
        mn = fminf(mn, fminf(fminf(v.x, v.y), fminf(v.z, v.w)));
        mx = fmaxf(mx, fmaxf(fmaxf(v.x, v.y), fmaxf(v.z, v.w)));
    }
    #pragma unroll
    for (int o = 16; o > 0; o >>= 1){
        mn = fminf(mn, __shfl_xor_sync(0xFFFFFFFFu, mn, o));
        mx = fmaxf(mx, __shfl_xor_sync(0xFFFFFFFFu, mx, o));
    }
    __shared__ float smn[8], smx[8];
    int wid = threadIdx.x >> 5, lane = threadIdx.x & 31;
    if (lane == 0){ smn[wid] = mn; smx[wid] = mx; }
    __syncthreads();
    if (threadIdx.x == 0){
        mn = smn[0]; mx = smx[0];
        #pragma unroll
        for (int w = 1; w < 8; ++w){ mn = fminf(mn, smn[w]); mx = fmaxf(mx, smx[w]); }
        g_mn[blockIdx.x] = mn;
        g_mx[blockIdx.x] = mx;
    }
}

// 6-tap packed MAC: taps [GW0,GW1,GW2,GW3,GW2,GW1]
#define HMAC(d, v0, v1, v2, v3, v4, v5) \
    d = mul2((v0), W0); d = fma2((v1), W1, d); d = fma2((v2), W2, d); \
    d = fma2((v3), W3, d); d = fma2((v4), W2, d); d = fma2((v5), W1, d)

// load one input row (both tensors) into register set S (S literal 0..2)
#define LOADROW(S, XR, YR) do { \
    rx[S][0] = *(const float2*)(XR); \
    rx[S][1] = *(const float2*)((const char*)(XR) + d1); \
    rx[S][2] = *(const float2*)((const char*)(XR) + d2); \
    rx[S][3] = *(const float2*)((const char*)(XR) + d3); \
    ry[S][0] = *(const float2*)(YR); \
    ry[S][1] = *(const float2*)((const char*)(YR) + d1); \
    ry[S][2] = *(const float2*)((const char*)(YR) + d2); \
    ry[S][3] = *(const float2*)((const char*)(YR) + d3); \
} while(0)

// One row-step. P literal 0..5. DOOUT/DOLOAD/DOPREF compile-time 0/1.
// Computes row from set P%3; LDGs 2 rows ahead into set (P+2)%3;
// L2-prefetches 6 rows ahead; emits one output row.
#define ROW_STEP(P, DOOUT, DOLOAD, DOPREF) do { \
    if (DOPREF){ pref2(xp); pref2(yp); xp += IMG_W; yp += IMG_W; } \
    if (DOLOAD){ LOADROW(((P)+2)%3, xr, yr); xr += IMG_W; yr += IMG_W; } \
    { \
        float2 X0_ = rx[(P)%3][0], X1_ = rx[(P)%3][1], X2_ = rx[(P)%3][2], X3_ = rx[(P)%3][3]; \
        float2 Y0_ = ry[(P)%3][0], Y1_ = ry[(P)%3][1], Y2_ = ry[(P)%3][2], Y3_ = ry[(P)%3][3]; \
        ull xp0_ = pk2(X0_.x, X0_.y), xp1_ = pk2(X1_.x, X1_.y); \
        ull xp2_ = pk2(X2_.x, X2_.y), xp3_ = pk2(X3_.x, X3_.y); \
        ull yp0_ = pk2(Y0_.x, Y0_.y), yp1_ = pk2(Y1_.x, Y1_.y); \
        ull yp2_ = pk2(Y2_.x, Y2_.y), yp3_ = pk2(Y3_.x, Y3_.y); \
        ull pp0_ = fma2(yp0_, yp0_, mul2(xp0_, xp0_)); \
        ull pp1_ = fma2(yp1_, yp1_, mul2(xp1_, xp1_)); \
        ull pp2_ = fma2(yp2_, yp2_, mul2(xp2_, xp2_)); \
        ull pp3_ = fma2(yp3_, yp3_, mul2(xp3_, xp3_)); \
        ull qq0_ = mul2(xp0_, yp0_), qq1_ = mul2(xp1_, yp1_); \
        ull qq2_ = mul2(xp2_, yp2_), qq3_ = mul2(xp3_, yp3_); \
        { ull d_; HMAC(d_, xp0_, pk2(X0_.y, X1_.x), xp1_, pk2(X1_.y, X2_.x), xp2_, pk2(X2_.y, X3_.x)); ring[(P)][0] = d_; } \
        { ull d_; HMAC(d_, yp0_, pk2(Y0_.y, Y1_.x), yp1_, pk2(Y1_.y, Y2_.x), yp2_, pk2(Y2_.y, Y3_.x)); ring[(P)][1] = d_; } \
        { ull d_; HMAC(d_, pp0_, pk2(hi2(pp0_), lo2(pp1_)), pp1_, pk2(hi2(pp1_), lo2(pp2_)), pp2_, pk2(hi2(pp2_), lo2(pp3_))); ring[(P)][2] = d_; } \
        { ull d_; HMAC(d_, qq0_, pk2(hi2(qq0_), lo2(qq1_)), qq1_, pk2(hi2(qq1_), lo2(qq2_)), qq2_, pk2(hi2(qq2_), lo2(qq3_))); ring[(P)][3] = d_; } \
    } \
    if (DOOUT){ \
        ull v0_, v1_, v2_, v3_; \
        HMAC(v0_, ring[((P)+1)%6][0], ring[((P)+2)%6][0], ring[((P)+3)%6][0], ring[((P)+4)%6][0], ring[((P)+5)%6][0], ring[(P)][0]); \
        HMAC(v1_, ring[((P)+1)%6][1], ring[((P)+2)%6][1], ring[((P)+3)%6][1], ring[((P)+4)%6][1], ring[((P)+5)%6][1], ring[(P)][1]); \
        HMAC(v2_, ring[((P)+1)%6][2], ring[((P)+2)%6][2], ring[((P)+3)%6][2], ring[((P)+4)%6][2], ring[((P)+5)%6][2], ring[(P)][2]); \
        HMAC(v3_, ring[((P)+1)%6][3], ring[((P)+2)%6][3], ring[((P)+3)%6][3], ring[((P)+4)%6][3], ring[((P)+5)%6][3], ring[(P)][3]); \
        ull mu12_ = mul2(v0_, v1_); \
        ull msum_ = fma2(v1_, v1_, mul2(v0_, v0_)); \
        ull t1_ = fma2(mu12_, NTWO, fma2(v3_, TWO, C2p)); \
        ull t2_ = fma2(msum_, NONE, add2(v2_, C2p)); \
        ull num_ = mul2(fma2(mu12_, TWO, C1p), t1_); \
        ull den_ = mul2(add2(msum_, C1p), t2_); \
        float nl_ = lo2(num_), nh_ = hi2(num_); \
        float dl_ = lo2(den_), dh_ = hi2(den_); \
        if (hi_ok)      acc += __fdividef(fmaf(nl_, dh_, nh_ * dl_), dl_ * dh_); \
        else if (lo_ok) acc += __fdividef(nl_, dl_); \
    } \
} while(0)

__global__ void __launch_bounds__(256, 2)
k_ssim(const float* __restrict__ X, const float* __restrict__ Y,
       float* __restrict__ out, int nblk, double inv_n){
    __shared__ float    smn[8], smx[8], sC[2];
    __shared__ double   sd[8];
    __shared__ unsigned s_tick;

    const int tid   = threadIdx.x;
    const int c0    = tid * 2;
    const int bx    = blockIdx.x;
    const int strip = bx % NSTR;
    const int img   = bx / NSTR;
    const int base  = strip * STRIP;
    const float* xi = X + (size_t)img * (IMG_W * IMG_W);
    const float* yi = Y + (size_t)img * (IMG_W * IMG_W);
    const bool lo_ok = (c0     < OUT_W);
    const bool hi_ok = (c0 + 1 < OUT_W);

    // clamped column byte deltas (edge threads read in-bounds garbage; masked)
    const int o0 = c0;
    const int d1 = (min(c0 + 2, 510) - c0) * 4;
    const int d2 = (min(c0 + 4, 510) - c0) * 4;
    const int d3 = (min(c0 + 6, 510) - c0) * 4;

    // running row pointers: xr/yr -> next LDG row (base+2); xp/yp -> prefetch row (base+6)
    const float* xr = xi + (size_t)(base + 2) * IMG_W + o0;
    const float* yr = yi + (size_t)(base + 2) * IMG_W + o0;
    const float* xp = xi + (size_t)(base + 6) * IMG_W + o0;
    const float* yp = yi + (size_t)(base + 6) * IMG_W + o0;

    // ---- reduce min/max partials -> C1, C2 ----
    {
        float mn = 3.4028235e38f, mx = -3.4028235e38f;
        for (int i = tid; i < NB_MM; i += 256){
            mn = fminf(mn, g_mn[i]);
            mx = fmaxf(mx, g_mx[i]);
        }
        #pragma unroll
        for (int o = 16; o > 0; o >>= 1){
            mn = fminf(mn, __shfl_xor_sync(0xFFFFFFFFu, mn, o));
            mx = fmaxf(mx, __shfl_xor_sync(0xFFFFFFFFu, mx, o));
        }
        int wid = tid >> 5, lane = tid & 31;
        if (lane == 0){ smn[wid] = mn; smx[wid] = mx; }
    }

    // register pipeline: 3 rotating row sets
    float2 rx[3][4], ry[3][4];
    {
        const float* x0 = xi + (size_t)base * IMG_W + o0;
        const float* y0 = yi + (size_t)base * IMG_W + o0;
        LOADROW(0, x0, y0);
        LOADROW(1, x0 + IMG_W, y0 + IMG_W);
        #pragma unroll
        for (int r = 2; r < 6; ++r){
            pref2(x0 + (size_t)r * IMG_W);
            pref2(y0 + (size_t)r * IMG_W);
        }
    }

    __syncthreads();
    if (tid == 0){
        float mn = smn[0], mx = smx[0];
        #pragma unroll
        for (int w = 1; w < 8; ++w){ mn = fminf(mn, smn[w]); mx = fmaxf(mx, smx[w]); }
        float Ldyn = (mx > 128.0f ? 255.0f : 1.0f) - (mn < -0.5f ? -1.0f : 0.0f);
        sC[0] = (0.01f * Ldyn) * (0.01f * Ldyn);
        sC[1] = (0.03f * Ldyn) * (0.03f * Ldyn);
    }
    __syncthreads();

    const float C1 = sC[0], C2 = sC[1];
    const ull W0  = pk2(GW0, GW0), W1 = pk2(GW1, GW1);
    const ull W2  = pk2(GW2, GW2), W3 = pk2(GW3, GW3);
    const ull C1p = pk2(C1, C1),   C2p = pk2(C2, C2);
    const ull TWO = pk2(2.0f, 2.0f), NTWO = pk2(-2.0f, -2.0f), NONE = pk2(-1.0f, -1.0f);

    ull ring[6][4];
    float acc = 0.0f;

    // ---- group 0 (rows 0..5): warm-up, first output at row 5 ----
    ROW_STEP(0, 0, 1, 1);
    ROW_STEP(1, 0, 1, 1);
    ROW_STEP(2, 0, 1, 1);
    ROW_STEP(3, 0, 1, 1);
    ROW_STEP(4, 0, 1, 1);
    ROW_STEP(5, 1, 1, 1);

    // ---- middle groups (rows 6..167): fully clean, no predicates ----
    #pragma unroll 1
    for (int i6 = 6; i6 < 168; i6 += 6){
        ROW_STEP(0, 1, 1, 1);
        ROW_STEP(1, 1, 1, 1);
        ROW_STEP(2, 1, 1, 1);
        ROW_STEP(3, 1, 1, 1);
        ROW_STEP(4, 1, 1, 1);
        ROW_STEP(5, 1, 1, 1);
    }

    // ---- tail group (rows 168..173): loads stop at row 173, no prefetch ----
    ROW_STEP(0, 1, 1, 0);   // loads row 170
    ROW_STEP(1, 1, 1, 0);   // loads row 171
    ROW_STEP(2, 1, 1, 0);   // loads row 172
    ROW_STEP(3, 1, 1, 0);   // loads row 173 (last input row)
    ROW_STEP(4, 1, 0, 0);
    ROW_STEP(5, 1, 0, 0);

    // ---- block reduction -> partial; last block finishes ----
    #pragma unroll
    for (int o = 16; o > 0; o >>= 1)
        acc += __shfl_xor_sync(0xFFFFFFFFu, acc, o);
    const int wid = tid >> 5, lane = tid & 31;
    if (lane == 0) smn[wid] = acc;
    __syncthreads();
    if (tid == 0){
        float s = smn[0];
        #pragma unroll
        for (int w = 1; w < 8; ++w) s += smn[w];
        g_part[bx] = s;
        __threadfence();
        s_tick = atomicAdd(&g_done, 1u);
    }
    __syncthreads();

    if (s_tick == (unsigned)(nblk - 1)){
        double s = 0.0;
        for (int i = tid; i < nblk; i += 256) s += (double)g_part[i];
        #pragma unroll
        for (int o = 16; o > 0; o >>= 1)
            s += __shfl_xor_sync(0xFFFFFFFFu, s, o);
        if (lane == 0) sd[wid] = s;
        __syncthreads();
        if (tid == 0){
            double t = 0.0;
            #pragma unroll
            for (int w = 0; w < 8; ++w) t += sd[w];
            out[0] = (float)((1.0 - t * inv_n) * 0.5);
            g_done = 0u;   // reset for next graph replay
        }
    }
}

// ---------------- launch --------------------------------------------------------
extern "C" void kernel_launch(void* const* d_in, const int* in_sizes, int n_in,
                              void* d_out, int out_size){
    const float* X = (const float*)d_in[0];  // y_pred
    const float* Y = (const float*)d_in[1];  // y_true

    const int nelem = in_sizes[0];
    const int nimg  = nelem / (IMG_W * IMG_W);
    const int nblk  = NSTR * nimg;
    const double n_out = (double)nimg * (double)OUT_W * (double)OUT_W;

    k_minmax<<<NB_MM, 256>>>((const float4*)X, nelem / 4);
    k_ssim<<<nblk, 256>>>(X, Y, (float*)d_out, nblk, 1.0 / n_out);
}